// round 14
// baseline (speedup 1.0000x reference)
#include <cuda_runtime.h>
#include <cstdint>

// WaveletLayer fused: db2 DWT -> scale -> inverse DWT -> ReLU, fully collapsed.
//
// QMF identity (hi[i] = (-1)^i lo[3-i]) collapses the chain to, per input
// pair (u,v) = (x[2m], x[2m+1]), with t = sqrt(3)/4:
//   p = 0.75u - t*v,  q = u - p
//   r = 0.25v - t*u,  s = v - r
//   out[2m]   = relu(k[m]*p + k[m+1]*q)
//   out[2m+1] = relu(k[m]*r + k[m+1]*s)
// Boundary/padding contributions cancel identically.
//
// R14: TMA-style double buffer. Persistent blocks (1184 = 8/SM x 256 thr)
// stride over 8192 half-row tiles. cp.async.bulk (register-free, issued by
// one elected thread) fills stage s^1 with tile t+GRID's x (8192B) and K
// (4112B, 16B-aligned-down base; verified in-bounds for all tiles) while all
// warps compute tile t from stage s. mbarrier complete_tx signals fill
// completion. This breaks the load-behind-compute serialization that capped
// R12/R13 without the register cost that capped R6/R7.

#define NCOL   4096
#define LOUT   2049
#define NT     256
#define TILES  8192
#define GRID   1184        // 8 blocks/SM x 148 SMs
#define XB     8192        // x bytes per tile (2048 floats)
#define KB     4112        // K bytes per tile (1028 floats, 16B multiple)
#define TXB    (XB + KB)

__device__ __forceinline__ uint32_t smem_u32(const void* p) {
    uint32_t a;
    asm("{ .reg .u64 t; cvta.to.shared.u64 t, %1; cvt.u32.u64 %0, t; }"
        : "=r"(a) : "l"(p));
    return a;
}

__device__ __forceinline__ void bulk_g2s(uint32_t dst, const void* src,
                                         uint32_t bytes, uint32_t bar) {
    asm volatile(
        "cp.async.bulk.shared::cluster.global.mbarrier::complete_tx::bytes "
        "[%0], [%1], %2, [%3];"
        :: "r"(dst), "l"(src), "r"(bytes), "r"(bar) : "memory");
}

__device__ __forceinline__ void mbar_init(uint32_t bar, uint32_t cnt) {
    asm volatile("mbarrier.init.shared.b64 [%0], %1;" :: "r"(bar), "r"(cnt) : "memory");
}

__device__ __forceinline__ void mbar_expect_tx(uint32_t bar, uint32_t bytes) {
    asm volatile("mbarrier.arrive.expect_tx.shared.b64 _, [%0], %1;"
                 :: "r"(bar), "r"(bytes) : "memory");
}

__device__ __forceinline__ void mbar_wait(uint32_t bar, uint32_t parity) {
    asm volatile(
        "{\n\t"
        ".reg .pred P;\n\t"
        "WL_%=:\n\t"
        "mbarrier.try_wait.parity.acquire.cta.shared::cta.b64 P, [%0], %1, 0x989680;\n\t"
        "@P bra.uni WD_%=;\n\t"
        "bra.uni WL_%=;\n\t"
        "WD_%=:\n\t"
        "}"
        :: "r"(bar), "r"(parity) : "memory");
}

__global__ __launch_bounds__(NT) void wavelet_fused_kernel(
    const float* __restrict__ x,
    const float* __restrict__ kern,
    float* __restrict__ out)
{
    __shared__ __align__(16) float sx[2][XB / 4];
    __shared__ __align__(16) float sk[2][KB / 4];
    __shared__ __align__(8)  uint64_t mbar[2];

    const int tid = threadIdx.x;

    const uint32_t bar0 = smem_u32(&mbar[0]);
    const uint32_t bar1 = smem_u32(&mbar[1]);
    const uint32_t sx0  = smem_u32(&sx[0][0]);
    const uint32_t sx1  = smem_u32(&sx[1][0]);
    const uint32_t sk0  = smem_u32(&sk[0][0]);
    const uint32_t sk1  = smem_u32(&sk[1][0]);

    if (tid == 0) {
        mbar_init(bar0, 1);
        mbar_init(bar1, 1);
    }
    __syncthreads();

    int t = blockIdx.x;

    // Prologue: fill stage 0 with tile t
    if (tid == 0) {
        const int row = t >> 1;
        const int w0  = row * LOUT + (t & 1) * 1024;
        const int d0  = w0 & 3;
        mbar_expect_tx(bar0, TXB);
        bulk_g2s(sx0, x + (row * NCOL + (t & 1) * 2048), XB, bar0);
        bulk_g2s(sk0, kern + (w0 - d0), KB, bar0);
    }

    int s = 0, ph0 = 0, ph1 = 0;

    while (t < TILES) {
        const int tn = t + GRID;
        // Issue next tile's fill into the other stage (register-free, async)
        if (tn < TILES && tid == 0) {
            const int nrow = tn >> 1;
            const int nw0  = nrow * LOUT + (tn & 1) * 1024;
            const int nd   = nw0 & 3;
            const uint32_t nbar = s ? bar0 : bar1;
            mbar_expect_tx(nbar, TXB);
            bulk_g2s(s ? sx0 : sx1, x + (nrow * NCOL + (tn & 1) * 2048), XB, nbar);
            bulk_g2s(s ? sk0 : sk1, kern + (nw0 - nd), KB, nbar);
        }

        // Wait for current stage
        if (s == 0) { mbar_wait(bar0, ph0); ph0 ^= 1; }
        else        { mbar_wait(bar1, ph1); ph1 ^= 1; }

        // ---- compute tile t from stage s ----
        const int row = t >> 1;
        const int w0  = row * LOUT + (t & 1) * 1024;
        const int d   = w0 & 3;                    // block-uniform
        const int lp  = tid * 4;                   // local pair index 0..1020

        const float* sxp = (s == 0 ? sx[0] : sx[1]);
        const float* skp = (s == 0 ? sk[0] : sk[1]);

        const float4 X0 = *reinterpret_cast<const float4*>(sxp + tid * 8);
        const float4 X1 = *reinterpret_cast<const float4*>(sxp + tid * 8 + 4);
        const float4 F0 = *reinterpret_cast<const float4*>(skp + lp);
        const float4 F1 = *reinterpret_cast<const float4*>(skp + lp + 4);

        float k0, k1, k2, k3, k4;
        if (d == 0)      { k0 = F0.x; k1 = F0.y; k2 = F0.z; k3 = F0.w; k4 = F1.x; }
        else if (d == 1) { k0 = F0.y; k1 = F0.z; k2 = F0.w; k3 = F1.x; k4 = F1.y; }
        else if (d == 2) { k0 = F0.z; k1 = F0.w; k2 = F1.x; k3 = F1.y; k4 = F1.z; }
        else             { k0 = F0.w; k1 = F1.x; k2 = F1.y; k3 = F1.z; k4 = F1.w; }

        const float T = 0.43301270189221932f;  // sqrt(3)/4
        float u, v, p, q, rr, ss;
        float4 r0, r1;

        u = X0.x; v = X0.y;
        p = fmaf(-T, v, 0.75f * u); q = u - p;
        rr = fmaf(-T, u, 0.25f * v); ss = v - rr;
        r0.x = fmaxf(fmaf(k1, q,  k0 * p),  0.0f);
        r0.y = fmaxf(fmaf(k1, ss, k0 * rr), 0.0f);

        u = X0.z; v = X0.w;
        p = fmaf(-T, v, 0.75f * u); q = u - p;
        rr = fmaf(-T, u, 0.25f * v); ss = v - rr;
        r0.z = fmaxf(fmaf(k2, q,  k1 * p),  0.0f);
        r0.w = fmaxf(fmaf(k2, ss, k1 * rr), 0.0f);

        u = X1.x; v = X1.y;
        p = fmaf(-T, v, 0.75f * u); q = u - p;
        rr = fmaf(-T, u, 0.25f * v); ss = v - rr;
        r1.x = fmaxf(fmaf(k3, q,  k2 * p),  0.0f);
        r1.y = fmaxf(fmaf(k3, ss, k2 * rr), 0.0f);

        u = X1.z; v = X1.w;
        p = fmaf(-T, v, 0.75f * u); q = u - p;
        rr = fmaf(-T, u, 0.25f * v); ss = v - rr;
        r1.z = fmaxf(fmaf(k4, q,  k3 * p),  0.0f);
        r1.w = fmaxf(fmaf(k4, ss, k3 * rr), 0.0f);

        float4* o4 = reinterpret_cast<float4*>(
            out + (row * NCOL + (t & 1) * 2048 + tid * 8));
        __stcs(o4,     r0);
        __stcs(o4 + 1, r1);

        // All threads done reading stage s before it gets refilled (2 iters out)
        __syncthreads();

        s ^= 1;
        t = tn;
    }
}

extern "C" void kernel_launch(void* const* d_in, const int* in_sizes, int n_in,
                              void* d_out, int out_size)
{
    const float* x    = (const float*)d_in[0];
    const float* kern = (const float*)d_in[1];
    float*       out  = (float*)d_out;

    wavelet_fused_kernel<<<GRID, NT>>>(x, kern, out);
}

// round 15
// speedup vs baseline: 1.1606x; 1.1606x over previous
#include <cuda_runtime.h>
#include <cstdint>

// WaveletLayer fused: db2 DWT -> scale -> inverse DWT -> ReLU, fully collapsed.
//
// QMF identity (hi[i] = (-1)^i lo[3-i]) collapses the chain to, per input
// pair (u,v) = (x[2m], x[2m+1]), with t = sqrt(3)/4:
//   p = 0.75u - t*v,  q = u - p
//   r = 0.25v - t*u,  s = v - r
//   out[2m]   = relu(k[m]*p + k[m+1]*q)
//   out[2m+1] = relu(k[m]*r + k[m+1]*s)
// Boundary/padding contributions cancel identically.
//
// R15 = R11 (best: flat grid, one 512-thread block per row, __ldcs x,
// __stcs out, K = one LDG.128 + shfl dedup) with the x load and out store
// widened to Blackwell 256-bit accesses (ld/st.global.v8.b32, 32B-aligned):
// half the memory requests for 2/3 of the traffic, wider DRAM bursts.

#define NCOL 4096
#define LOUT 2049
#define NT   512
#define FULL 0xffffffffu

__global__ __launch_bounds__(NT) void wavelet_fused_kernel(
    const float* __restrict__ x,
    const float* __restrict__ kern,
    float* __restrict__ out)
{
    const int row  = blockIdx.x;
    const int m0   = threadIdx.x * 4;     // first pair index (0..2044)
    const int base = 2 * m0;              // first output column (32B-aligned)
    const int lane = threadIdx.x & 31;

    // ---- x[base .. base+7]: ONE 256-bit evict-first load ----
    uint32_t xv[8];
    {
        const float* xp = x + (size_t)row * NCOL + base;   // 32B-aligned
        asm volatile(
            "ld.global.cs.v8.b32 {%0,%1,%2,%3,%4,%5,%6,%7}, [%8];"
            : "=r"(xv[0]), "=r"(xv[1]), "=r"(xv[2]), "=r"(xv[3]),
              "=r"(xv[4]), "=r"(xv[5]), "=r"(xv[6]), "=r"(xv[7])
            : "l"(xp));
    }
    const float u0 = __uint_as_float(xv[0]), v0 = __uint_as_float(xv[1]);
    const float u1 = __uint_as_float(xv[2]), v1 = __uint_as_float(xv[3]);
    const float u2 = __uint_as_float(xv[4]), v2 = __uint_as_float(xv[5]);
    const float u3 = __uint_as_float(xv[6]), v3 = __uint_as_float(xv[7]);

    // ---- K window K[m0..m0+4]: one LDG.128 + shfl dedup (R11-validated) ----
    // Aligned cover [w-d, w-d+8); F1(lane) == F0(lane+1); lane 31 loads F1.
    // (Tail-safe: last row has d=3, F1 ends exactly at kern's last element.)
    const int w = LOUT * row + m0;
    const int d = w & 3;
    const float4* kp = reinterpret_cast<const float4*>(kern + (w - d));
    float4 F0 = kp[0];
    float4 F1;
    F1.x = __shfl_down_sync(FULL, F0.x, 1);
    F1.y = __shfl_down_sync(FULL, F0.y, 1);
    F1.z = __shfl_down_sync(FULL, F0.z, 1);
    F1.w = __shfl_down_sync(FULL, F0.w, 1);
    if (lane == 31) F1 = kp[1];

    float k0, k1, k2, k3, k4;
    if (d == 0)      { k0 = F0.x; k1 = F0.y; k2 = F0.z; k3 = F0.w; k4 = F1.x; }
    else if (d == 1) { k0 = F0.y; k1 = F0.z; k2 = F0.w; k3 = F1.x; k4 = F1.y; }
    else if (d == 2) { k0 = F0.z; k1 = F0.w; k2 = F1.x; k3 = F1.y; k4 = F1.z; }
    else             { k0 = F0.w; k1 = F1.x; k2 = F1.y; k3 = F1.z; k4 = F1.w; }

    const float T = 0.43301270189221932f;  // sqrt(3)/4

    float p, q, rr, ss;
    uint32_t r[8];

    p  = fmaf(-T, v0, 0.75f * u0); q  = u0 - p;
    rr = fmaf(-T, u0, 0.25f * v0); ss = v0 - rr;
    r[0] = __float_as_uint(fmaxf(fmaf(k1, q,  k0 * p),  0.0f));
    r[1] = __float_as_uint(fmaxf(fmaf(k1, ss, k0 * rr), 0.0f));

    p  = fmaf(-T, v1, 0.75f * u1); q  = u1 - p;
    rr = fmaf(-T, u1, 0.25f * v1); ss = v1 - rr;
    r[2] = __float_as_uint(fmaxf(fmaf(k2, q,  k1 * p),  0.0f));
    r[3] = __float_as_uint(fmaxf(fmaf(k2, ss, k1 * rr), 0.0f));

    p  = fmaf(-T, v2, 0.75f * u2); q  = u2 - p;
    rr = fmaf(-T, u2, 0.25f * v2); ss = v2 - rr;
    r[4] = __float_as_uint(fmaxf(fmaf(k3, q,  k2 * p),  0.0f));
    r[5] = __float_as_uint(fmaxf(fmaf(k3, ss, k2 * rr), 0.0f));

    p  = fmaf(-T, v3, 0.75f * u3); q  = u3 - p;
    rr = fmaf(-T, u3, 0.25f * v3); ss = v3 - rr;
    r[6] = __float_as_uint(fmaxf(fmaf(k4, q,  k3 * p),  0.0f));
    r[7] = __float_as_uint(fmaxf(fmaf(k4, ss, k3 * rr), 0.0f));

    // ---- out[base .. base+7]: ONE 256-bit evict-first store ----
    {
        float* op = out + (size_t)row * NCOL + base;       // 32B-aligned
        asm volatile(
            "st.global.cs.v8.b32 [%0], {%1,%2,%3,%4,%5,%6,%7,%8};"
            :: "l"(op),
               "r"(r[0]), "r"(r[1]), "r"(r[2]), "r"(r[3]),
               "r"(r[4]), "r"(r[5]), "r"(r[6]), "r"(r[7])
            : "memory");
    }
}

extern "C" void kernel_launch(void* const* d_in, const int* in_sizes, int n_in,
                              void* d_out, int out_size)
{
    const float* x    = (const float*)d_in[0];
    const float* kern = (const float*)d_in[1];
    float*       out  = (float*)d_out;

    wavelet_fused_kernel<<<4096, NT>>>(x, kern, out);  // one block per row
}

// round 16
// speedup vs baseline: 1.4962x; 1.2892x over previous
#include <cuda_runtime.h>

// WaveletLayer fused: db2 DWT -> scale -> inverse DWT -> ReLU, fully collapsed.
//
// QMF identity (hi[i] = (-1)^i lo[3-i]) collapses the chain to, per input
// pair (u,v) = (x[2m], x[2m+1]), with t = sqrt(3)/4:
//   p = 0.75u - t*v,  q = u - p
//   r = 0.25v - t*u,  s = v - r
//   out[2m]   = relu(k[m]*p + k[m+1]*q)
//   out[2m+1] = relu(k[m]*r + k[m+1]*s)
// Boundary/padding contributions cancel identically.
//
// R16 = R11 (validated best: flat grid, one 512-thread block per row,
// __ldcs 128-bit x loads, __stcs 128-bit out stores, K = one LDG.128 +
// shfl_down dedup, uniform d-select, 30 regs) with one micro-fix: the K
// load is issued FIRST, since it heads the longest dependency chain
// (LDG -> 4x SHFL -> select -> final FMAs), while x feeds only two FMA
// levels. Identical memory traffic and hints to R11's proven 21.98us
// bench steady state.

#define NCOL 4096
#define LOUT 2049
#define NT   512
#define FULL 0xffffffffu

__global__ __launch_bounds__(NT) void wavelet_fused_kernel(
    const float* __restrict__ x,
    const float* __restrict__ kern,
    float* __restrict__ out)
{
    const int row  = blockIdx.x;
    const int m0   = threadIdx.x * 4;     // first pair index (0..2044)
    const int base = 2 * m0;              // first output column
    const int lane = threadIdx.x & 31;

    // ---- K first: heads the longest chain (LDG -> shfl x4 -> select) ----
    // K window K[m0..m0+4]: aligned cover [w-d, w-d+8), d = row & 3 uniform.
    // F1(lane) == F0(lane+1) -> one LDG + 4 shfl; lane 31 loads F1 directly.
    // (Tail-safe: last row has d=3, F1 ends exactly at kern's last element.)
    const int w = LOUT * row + m0;
    const int d = w & 3;
    const float4* kp = reinterpret_cast<const float4*>(kern + (w - d));
    float4 F0 = kp[0];

    // ---- x[base .. base+7]: two aligned evict-first float4 loads ----
    const float4* x4 = reinterpret_cast<const float4*>(x + (size_t)row * NCOL + base);
    float4 X0 = __ldcs(x4);
    float4 X1 = __ldcs(x4 + 1);

    float4 F1;
    F1.x = __shfl_down_sync(FULL, F0.x, 1);
    F1.y = __shfl_down_sync(FULL, F0.y, 1);
    F1.z = __shfl_down_sync(FULL, F0.z, 1);
    F1.w = __shfl_down_sync(FULL, F0.w, 1);
    if (lane == 31) F1 = kp[1];

    float k0, k1, k2, k3, k4;
    if (d == 0)      { k0 = F0.x; k1 = F0.y; k2 = F0.z; k3 = F0.w; k4 = F1.x; }
    else if (d == 1) { k0 = F0.y; k1 = F0.z; k2 = F0.w; k3 = F1.x; k4 = F1.y; }
    else if (d == 2) { k0 = F0.z; k1 = F0.w; k2 = F1.x; k3 = F1.y; k4 = F1.z; }
    else             { k0 = F0.w; k1 = F1.x; k2 = F1.y; k3 = F1.z; k4 = F1.w; }

    const float T = 0.43301270189221932f;  // sqrt(3)/4

    float u, v, p, q, rr, ss;
    float4 r0, r1;

    u = X0.x; v = X0.y;
    p = fmaf(-T, v, 0.75f * u); q = u - p;
    rr = fmaf(-T, u, 0.25f * v); ss = v - rr;
    r0.x = fmaxf(fmaf(k1, q,  k0 * p),  0.0f);
    r0.y = fmaxf(fmaf(k1, ss, k0 * rr), 0.0f);

    u = X0.z; v = X0.w;
    p = fmaf(-T, v, 0.75f * u); q = u - p;
    rr = fmaf(-T, u, 0.25f * v); ss = v - rr;
    r0.z = fmaxf(fmaf(k2, q,  k1 * p),  0.0f);
    r0.w = fmaxf(fmaf(k2, ss, k1 * rr), 0.0f);

    u = X1.x; v = X1.y;
    p = fmaf(-T, v, 0.75f * u); q = u - p;
    rr = fmaf(-T, u, 0.25f * v); ss = v - rr;
    r1.x = fmaxf(fmaf(k3, q,  k2 * p),  0.0f);
    r1.y = fmaxf(fmaf(k3, ss, k2 * rr), 0.0f);

    u = X1.z; v = X1.w;
    p = fmaf(-T, v, 0.75f * u); q = u - p;
    rr = fmaf(-T, u, 0.25f * v); ss = v - rr;
    r1.z = fmaxf(fmaf(k4, q,  k3 * p),  0.0f);
    r1.w = fmaxf(fmaf(k4, ss, k3 * rr), 0.0f);

    float4* o4 = reinterpret_cast<float4*>(out + (size_t)row * NCOL + base);
    __stcs(o4,     r0);
    __stcs(o4 + 1, r1);
}

extern "C" void kernel_launch(void* const* d_in, const int* in_sizes, int n_in,
                              void* d_out, int out_size)
{
    const float* x    = (const float*)d_in[0];
    const float* kern = (const float*)d_in[1];
    float*       out  = (float*)d_out;

    wavelet_fused_kernel<<<4096, NT>>>(x, kern, out);  // one block per row
}

// round 17
// speedup vs baseline: 1.4985x; 1.0015x over previous
#include <cuda_runtime.h>

// WaveletLayer fused: db2 DWT -> scale -> inverse DWT -> ReLU, fully collapsed.
//
// QMF identity (hi[i] = (-1)^i lo[3-i]) collapses the chain to, per input
// pair (u,v) = (x[2m], x[2m+1]), with t = sqrt(3)/4:
//   p = 0.75u - t*v,  q = u - p
//   r = 0.25v - t*u,  s = v - r
//   out[2m]   = relu(k[m]*p + k[m+1]*q)
//   out[2m+1] = relu(k[m]*r + k[m+1]*s)
// Boundary/padding contributions cancel identically.
//
// R17 = R16 (validated best: flat grid, one 512-thread block per row, K LDG
// issued first, __ldcs 128-bit x loads, __stcs 128-bit out stores, K dedup
// via shfl_down, uniform d-select, 30 regs) + tail-shortening micro-edits:
//   - r0 is stored as soon as its inputs (k0..k2, X0) are ready, overlapping
//     STG issue/drain with the second half's FMAs.
//   - the F0-only part of the d-select is hoisted above the shuffle results
//     so X0's FMAs can start before the SHFL chain completes.

#define NCOL 4096
#define LOUT 2049
#define NT   512
#define FULL 0xffffffffu

__global__ __launch_bounds__(NT) void wavelet_fused_kernel(
    const float* __restrict__ x,
    const float* __restrict__ kern,
    float* __restrict__ out)
{
    const int row  = blockIdx.x;
    const int m0   = threadIdx.x * 4;     // first pair index (0..2044)
    const int base = 2 * m0;              // first output column
    const int lane = threadIdx.x & 31;

    // ---- K first: heads the longest chain ----
    // K window K[m0..m0+4]: aligned cover [w-d, w-d+8), d = row & 3 uniform.
    // F1(lane) == F0(lane+1) -> one LDG + 4 shfl; lane 31 loads F1 directly.
    // (Tail-safe: last row has d=3, F1 ends exactly at kern's last element.)
    const int w = LOUT * row + m0;
    const int d = w & 3;
    const float4* kp = reinterpret_cast<const float4*>(kern + (w - d));
    float4 F0 = kp[0];

    // ---- x[base .. base+7]: two aligned evict-first float4 loads ----
    const float4* x4 = reinterpret_cast<const float4*>(x + (size_t)row * NCOL + base);
    float4 X0 = __ldcs(x4);
    float4 X1 = __ldcs(x4 + 1);

    // F0-only part of the select: k0..k2 never need F1 (d <= 3 -> k0..k2
    // come from F0 except k2/k3 at high d; handle exactly below).
    float k0, k1, k2, k3, k4;
    if (d == 0)      { k0 = F0.x; k1 = F0.y; k2 = F0.z; }
    else if (d == 1) { k0 = F0.y; k1 = F0.z; k2 = F0.w; }
    else if (d == 2) { k0 = F0.z; k1 = F0.w; }
    else             { k0 = F0.w; }

    float4 F1;
    F1.x = __shfl_down_sync(FULL, F0.x, 1);
    F1.y = __shfl_down_sync(FULL, F0.y, 1);
    F1.z = __shfl_down_sync(FULL, F0.z, 1);
    F1.w = __shfl_down_sync(FULL, F0.w, 1);
    if (lane == 31) F1 = kp[1];

    if (d == 0)      { k3 = F0.w; k4 = F1.x; }
    else if (d == 1) { k3 = F1.x; k4 = F1.y; }
    else if (d == 2) { k2 = F1.x; k3 = F1.y; k4 = F1.z; }
    else             { k1 = F1.x; k2 = F1.y; k3 = F1.z; k4 = F1.w; }

    const float T = 0.43301270189221932f;  // sqrt(3)/4

    float u, v, p, q, rr, ss;
    float4 r0, r1;

    // ---- first half (needs k0..k2, X0) ----
    u = X0.x; v = X0.y;
    p = fmaf(-T, v, 0.75f * u); q = u - p;
    rr = fmaf(-T, u, 0.25f * v); ss = v - rr;
    r0.x = fmaxf(fmaf(k1, q,  k0 * p),  0.0f);
    r0.y = fmaxf(fmaf(k1, ss, k0 * rr), 0.0f);

    u = X0.z; v = X0.w;
    p = fmaf(-T, v, 0.75f * u); q = u - p;
    rr = fmaf(-T, u, 0.25f * v); ss = v - rr;
    r0.z = fmaxf(fmaf(k2, q,  k1 * p),  0.0f);
    r0.w = fmaxf(fmaf(k2, ss, k1 * rr), 0.0f);

    float4* o4 = reinterpret_cast<float4*>(out + (size_t)row * NCOL + base);
    __stcs(o4, r0);   // issue first store early; overlaps with second half

    // ---- second half (needs k2..k4, X1) ----
    u = X1.x; v = X1.y;
    p = fmaf(-T, v, 0.75f * u); q = u - p;
    rr = fmaf(-T, u, 0.25f * v); ss = v - rr;
    r1.x = fmaxf(fmaf(k3, q,  k2 * p),  0.0f);
    r1.y = fmaxf(fmaf(k3, ss, k2 * rr), 0.0f);

    u = X1.z; v = X1.w;
    p = fmaf(-T, v, 0.75f * u); q = u - p;
    rr = fmaf(-T, u, 0.25f * v); ss = v - rr;
    r1.z = fmaxf(fmaf(k4, q,  k3 * p),  0.0f);
    r1.w = fmaxf(fmaf(k4, ss, k3 * rr), 0.0f);

    __stcs(o4 + 1, r1);
}

extern "C" void kernel_launch(void* const* d_in, const int* in_sizes, int n_in,
                              void* d_out, int out_size)
{
    const float* x    = (const float*)d_in[0];
    const float* kern = (const float*)d_in[1];
    float*       out  = (float*)d_out;

    wavelet_fused_kernel<<<4096, NT>>>(x, kern, out);  // one block per row
}